// round 14
// baseline (speedup 1.0000x reference)
#include <cuda_runtime.h>
#include <math.h>

#define BB   8
#define FF   48
#define SS   64
#define DD   512
#define NHH  8
#define DHH  64
#define LLAY 4
#define DFFF 2048
#define MMM  64
#define LNEPS 1e-5f
#define GRID 128          // persistent blocks (<= SM count -> all co-resident)
#define NWARP (GRID*8)    // 1024 warps

// ---------------- scratch (device globals; allocation-free) ----------------
__device__ __align__(16) float g_q   [BB*DD];
__device__ __align__(16) float g_xb  [BB*DD];
__device__ __align__(16) float g_y   [BB*DD];
__device__ __align__(16) float g_r   [BB*DD];
__device__ __align__(16) float g_h   [BB*DFFF];
__device__ __align__(16) float g_K   [LLAY*BB*FF*DD];
__device__ __align__(16) float g_V   [LLAY*BB*FF*DD];
__device__ __align__(16) float g_XA  [LLAY*BB*FF*DD];
__device__ __align__(16) float g_E2  [BB*FF*DD];
__device__ __align__(16) float g_CW  [DD*MMM];
__device__ __align__(16) float g_cb  [DD];
__device__ __align__(16) float g_qh  [BB*FF*DD];
__device__ __align__(16) float g_kh  [BB*SS*DD];
__device__ __align__(16) float g_vh  [BB*SS*DD];
__device__ __align__(16) float g_tmpL[LLAY*BB*FF*DD];

// flag-array barrier: one flag per block + one generation word
__device__ __align__(128) unsigned g_flag[128];
__device__ __align__(128) unsigned g_gen [32];

// ---------------- helpers ----------------
__device__ __forceinline__ float warp_sum(float v){
#pragma unroll
    for (int o = 16; o; o >>= 1) v += __shfl_xor_sync(0xffffffffu, v, o);
    return v;
}
__device__ __forceinline__ float dot4(float4 a, float4 b){
    return a.x*b.x + a.y*b.y + a.z*b.z + a.w*b.w;
}
__device__ __forceinline__ float4 ld_cg4(const float* p){
    float4 v;
    asm volatile("ld.global.cg.v4.f32 {%0,%1,%2,%3}, [%4];"
                 : "=f"(v.x), "=f"(v.y), "=f"(v.z), "=f"(v.w) : "l"(p));
    return v;
}

// flag barrier: parallel release-arrivals; block 0 detects + releases g_gen;
// everyone polls g_gen with one acquire lane.
__device__ __forceinline__ void grid_sync(unsigned &phase){
    __syncthreads();
    if (threadIdx.x < 32){
        if (threadIdx.x == 0)
            asm volatile("st.release.gpu.u32 [%0], %1;"
                         :: "l"(&g_flag[blockIdx.x]), "r"(phase + 1u) : "memory");
        if (blockIdx.x == 0){
            unsigned m;
            do {
                unsigned v0,v1,v2,v3;
                asm volatile("ld.acquire.gpu.u32 %0, [%1];" : "=r"(v0) : "l"(&g_flag[threadIdx.x     ]) : "memory");
                asm volatile("ld.acquire.gpu.u32 %0, [%1];" : "=r"(v1) : "l"(&g_flag[threadIdx.x + 32]) : "memory");
                asm volatile("ld.acquire.gpu.u32 %0, [%1];" : "=r"(v2) : "l"(&g_flag[threadIdx.x + 64]) : "memory");
                asm volatile("ld.acquire.gpu.u32 %0, [%1];" : "=r"(v3) : "l"(&g_flag[threadIdx.x + 96]) : "memory");
                m = min(min(v0, v1), min(v2, v3));
#pragma unroll
                for (int o = 16; o; o >>= 1) m = min(m, __shfl_xor_sync(0xffffffffu, m, o));
            } while (m <= phase);
            if (threadIdx.x == 0)
                asm volatile("st.release.gpu.u32 [%0], %1;"
                             :: "l"(g_gen), "r"(phase + 1u) : "memory");
        }
        if (threadIdx.x == 0){
            unsigned cur;
            do {
                asm volatile("ld.acquire.gpu.u32 %0, [%1];" : "=r"(cur) : "l"(g_gen) : "memory");
            } while (cur <= phase);
        }
    }
    phase++;
    __syncthreads();
}

// ================= precompute kernels (5 launches before decode) =================

// launch 1: CA in-proj. z=0 q(content,384 rows), z=1 k(style,512), z=2 v(style,512)
__global__ void ca_inproj_kernel(const float* __restrict__ content, const float* __restrict__ style,
                                 const float* __restrict__ ca_in_w, const float* __restrict__ ca_in_b){
    int z = blockIdx.z;
    const float* X = (z == 0) ? content : style;
    int R = (z == 0) ? BB*FF : BB*SS;
    float* out = (z == 0) ? g_qh : (z == 1 ? g_kh : g_vh);
    const float* W = ca_in_w + (size_t)z*DD*DD;
    const float* bias = ca_in_b + z*DD;
    int warp = threadIdx.x >> 5, lane = threadIdx.x & 31;
    int n  = blockIdx.x * 8 + warp;
    int r0 = blockIdx.y * 8;
    if (r0 >= R) return;
    const float4* w4 = (const float4*)(W + (size_t)n * DD);
    const float* x = X + (size_t)r0 * DD;
    float acc[8] = {0.f,0.f,0.f,0.f,0.f,0.f,0.f,0.f};
#pragma unroll
    for (int q = 0; q < 4; q++){
        int i = lane + q*32;
        float4 wv = w4[i];
#pragma unroll
        for (int b = 0; b < 8; b++)
            acc[b] += dot4(wv, ((const float4*)(x + (size_t)b*DD))[i]);
    }
#pragma unroll
    for (int o = 16; o; o >>= 1){
#pragma unroll
        for (int b = 0; b < 8; b++) acc[b] += __shfl_xor_sync(0xffffffffu, acc[b], o);
    }
    float bv = bias[n];
#pragma unroll
    for (int b = 0; b < 8; b++)
        if (lane == b) out[(size_t)(r0 + b) * DD + n] = acc[b] + bv;
}

// launch 2: sel attention (nh=1, softmax over S=64), IN-PLACE on g_qh
__global__ void ca_attn_kernel(){
    int r = blockIdx.x;
    int b = r / FF;
    __shared__ __align__(16) float s_q[DD];
    __shared__ float s_p[SS];
    int tid = threadIdx.x, warp = tid >> 5, lane = tid & 31;
    for (int d = tid; d < DD; d += 256) s_q[d] = g_qh[(size_t)r*DD + d];
    __syncthreads();
    for (int s = warp; s < SS; s += 8){
        const float4* kr4 = (const float4*)(g_kh + (size_t)(b*SS + s)*DD);
        float a = 0.f;
#pragma unroll
        for (int q = 0; q < 4; q++){
            int i = lane + q*32;
            a += dot4(((const float4*)s_q)[i], kr4[i]);
        }
        a = warp_sum(a);
        if (lane == 0) s_p[s] = a * 0.04419417382415922f;
    }
    __syncthreads();
    if (warp == 0){
        float v0 = s_p[lane], v1 = s_p[lane + 32];
        float m = fmaxf(v0, v1);
#pragma unroll
        for (int o2 = 16; o2; o2 >>= 1) m = fmaxf(m, __shfl_xor_sync(0xffffffffu, m, o2));
        float e0 = expf(v0 - m), e1 = expf(v1 - m);
        float sm = warp_sum(e0 + e1);
        float inv = 1.f / sm;
        s_p[lane] = e0 * inv; s_p[lane + 32] = e1 * inv;
    }
    __syncthreads();
    for (int d = tid; d < DD; d += 256){
        float a = 0.f;
#pragma unroll 8
        for (int s = 0; s < SS; s++) a += s_p[s] * g_vh[(size_t)(b*SS + s)*DD + d];
        g_qh[(size_t)r*DD + d] = a;
    }
}

// launch 3: z=0 sel = g_qh @ ca_out; z=1..4: tmpL[l] = content @ xa_v[l]
__global__ void fused3_kernel(const float* __restrict__ content,
                              const float* __restrict__ ca_out_w, const float* __restrict__ ca_out_b,
                              const float* __restrict__ xa_in_w,  const float* __restrict__ xa_in_b,
                              float* __restrict__ sel){
    int z = blockIdx.z;
    const float *X, *W, *bias; float* out;
    if (z == 0){ X = g_qh; W = ca_out_w; bias = ca_out_b; out = sel; }
    else {
        int l = z - 1;
        X = content;
        W = xa_in_w + (size_t)l*3*DD*DD + 2*DD*DD;
        bias = xa_in_b + (size_t)l*3*DD + 2*DD;
        out = g_tmpL + (size_t)l*BB*FF*DD;
    }
    int warp = threadIdx.x >> 5, lane = threadIdx.x & 31;
    int n  = blockIdx.x * 8 + warp;
    int r0 = blockIdx.y * 8;
    const float4* w4 = (const float4*)(W + (size_t)n * DD);
    const float* x = X + (size_t)r0 * DD;
    float acc[8] = {0.f,0.f,0.f,0.f,0.f,0.f,0.f,0.f};
#pragma unroll
    for (int q = 0; q < 4; q++){
        int i = lane + q*32;
        float4 wv = w4[i];
#pragma unroll
        for (int b = 0; b < 8; b++)
            acc[b] += dot4(wv, ((const float4*)(x + (size_t)b*DD))[i]);
    }
#pragma unroll
    for (int o = 16; o; o >>= 1){
#pragma unroll
        for (int b = 0; b < 8; b++) acc[b] += __shfl_xor_sync(0xffffffffu, acc[b], o);
    }
    float bv = bias[n];
#pragma unroll
    for (int b = 0; b < 8; b++)
        if (lane == b) out[(size_t)(r0 + b) * DD + n] = acc[b] + bv;
}

// launch 4: XA[l] = tmpL[l] @ xa_out[l]
__global__ void xa2_kernel(const float* __restrict__ xa_out_w, const float* __restrict__ xa_out_b){
    int z = blockIdx.z;
    const float* X = g_tmpL + (size_t)z*BB*FF*DD;
    const float* W = xa_out_w + (size_t)z*DD*DD;
    const float* bias = xa_out_b + (size_t)z*DD;
    float* out = g_XA + (size_t)z*BB*FF*DD;
    int warp = threadIdx.x >> 5, lane = threadIdx.x & 31;
    int n  = blockIdx.x * 8 + warp;
    int r0 = blockIdx.y * 8;
    const float4* w4 = (const float4*)(W + (size_t)n * DD);
    const float* x = X + (size_t)r0 * DD;
    float acc[8] = {0.f,0.f,0.f,0.f,0.f,0.f,0.f,0.f};
#pragma unroll
    for (int q = 0; q < 4; q++){
        int i = lane + q*32;
        float4 wv = w4[i];
#pragma unroll
        for (int b = 0; b < 8; b++)
            acc[b] += dot4(wv, ((const float4*)(x + (size_t)b*DD))[i]);
    }
#pragma unroll
    for (int o = 16; o; o >>= 1){
#pragma unroll
        for (int b = 0; b < 8; b++) acc[b] += __shfl_xor_sync(0xffffffffu, acc[b], o);
    }
    float bv = bias[n];
#pragma unroll
    for (int b = 0; b < 8; b++)
        if (lane == b) out[(size_t)(r0 + b) * DD + n] = acc[b] + bv;
}

// launch 5: misc — e2 (3072 blocks) + CW fold (512) + x0 init (8) + flag reset (1)
__global__ void misc_kernel(const float* __restrict__ sel, const float* __restrict__ se_w,
                            const float* __restrict__ se_b, const float* __restrict__ style,
                            const float* __restrict__ mm_w, const float* __restrict__ mm_b,
                            const float* __restrict__ init_state){
    int bid = blockIdx.x, tid = threadIdx.x;
    if (bid < 3072){
        // E2[b,p,n] = sel[b,p?p-1:0]·W2[n,:] + se_b[n] + style[b,n] + PE[p,n]
        int bx = bid & 63, by = bid >> 6;
        int warp = tid >> 5, lane = tid & 31;
        int n  = bx * 8 + warp;
        int r0 = by * 8;
        int b  = r0 / FF;
        const float4* w4 = (const float4*)(se_w + (size_t)n * 1024 + 512);
        const float4* xr[8];
#pragma unroll
        for (int q = 0; q < 8; q++){
            int p  = (r0 + q) % FF;
            int ip = p ? (p - 1) : 0;
            xr[q] = (const float4*)(sel + ((size_t)b*FF + ip)*DD);
        }
        float acc[8] = {0.f,0.f,0.f,0.f,0.f,0.f,0.f,0.f};
#pragma unroll
        for (int i4 = 0; i4 < 4; i4++){
            int i = lane + i4*32;
            float4 wv = w4[i];
#pragma unroll
            for (int q = 0; q < 8; q++) acc[q] += dot4(wv, xr[q][i]);
        }
#pragma unroll
        for (int o = 16; o; o >>= 1){
#pragma unroll
            for (int q = 0; q < 8; q++) acc[q] += __shfl_xor_sync(0xffffffffu, acc[q], o);
        }
#pragma unroll
        for (int q = 0; q < 8; q++){
            if (lane == q){
                int p = (r0 + q) % FF;
                float pos = (float)(p % 30);
                const float LF = 9.210340371976184f / 512.f;
                float pe;
                if (n & 1) pe = cosf(pos * expf(-(float)(n - 1) * LF));
                else       pe = sinf(pos * expf(-(float)n       * LF));
                g_E2[((size_t)r0 + q)*DD + n] = acc[q] + se_b[n] + style[b*DD + n] + pe;
            }
        }
    } else if (bid < 3584){
        // CW[d,:] = W1[d,:] @ mm_w ; cb[d] = W1[d,:]·mm_b
        int d = bid - 3072;
        __shared__ float s_w1[DD];
        for (int k = tid; k < DD; k += 256) s_w1[k] = se_w[(size_t)d*1024 + k];
        __syncthreads();
        if (tid < 64){
            int j = tid;
            float a = 0.f;
            for (int k = 0; k < DD; k++) a += s_w1[k] * mm_w[(size_t)k*MMM + j];
            g_CW[(size_t)d*MMM + j] = a;
            if (j == 0){
                float c = 0.f;
                for (int k = 0; k < DD; k++) c += s_w1[k] * mm_b[k];
                g_cb[d] = c;
            }
        }
    } else if (bid < 3592){
        // x0[b] = feat@W1^T + sel[b,0]@W2^T + se_b + style[b] + PE[0]
        int b = bid - 3584;
        __shared__ __align__(16) float s_feat[DD];
        for (int d = tid; d < DD; d += 256){
            float a = mm_b[d];
            const float* mw = mm_w + (size_t)d * MMM;
            const float* is = init_state + b * MMM;
#pragma unroll
            for (int k = 0; k < MMM; k++) a += is[k] * mw[k];
            s_feat[d] = a;
        }
        __syncthreads();
        for (int d = tid; d < DD; d += 256){
            const float4* w1 = (const float4*)(se_w + (size_t)d * 1024);
            const float4* w2 = (const float4*)(se_w + (size_t)d * 1024 + 512);
            const float4* s0 = (const float4*)(sel + (size_t)b*FF*DD);
            float a1 = 0.f, a2 = 0.f;
#pragma unroll
            for (int i = 0; i < 128; i++){
                a1 += dot4(((const float4*)s_feat)[i], w1[i]);
                a2 += dot4(s0[i], w2[i]);
            }
            float pe = (d & 1) ? 1.f : 0.f;   // PE[0]: sin(0)=0 (even), cos(0)=1 (odd)
            g_xb[b*DD + d] = a1 + a2 + se_b[d] + style[b*DD + d] + pe;
        }
    } else {
        if (tid < 128) g_flag[tid] = 0;
        if (tid == 128) g_gen[0] = 0;
    }
}

// ================= persistent decode kernel (chip-wide, flag barrier) =========
__global__ void __launch_bounds__(256, 1) decode_kernel(
    const float* __restrict__ sa_in_w,  const float* __restrict__ sa_in_b,
    const float* __restrict__ sa_out_w, const float* __restrict__ sa_out_b,
    const float* __restrict__ ff1_w,    const float* __restrict__ ff1_b,
    const float* __restrict__ ff2_w,    const float* __restrict__ ff2_b,
    const float* __restrict__ ln_g,     const float* __restrict__ ln_b,
    const float* __restrict__ mmr_w,    const float* __restrict__ mmr_b,
    float* __restrict__ dec_out)
{
    int tid = threadIdx.x, w = tid >> 5, lane = tid & 31;
    int gw  = blockIdx.x * 8 + w;
    int myb = blockIdx.x >> 4;
    int sub = blockIdx.x & 15;
    unsigned phase = 0;
    __shared__ __align__(16) float s_x [BB][DD];   // all-batch state (x, then x2)
    __shared__ __align__(16) float s_attn[DD];
    __shared__ __align__(16) float s_qb[8][DHH];
    __shared__ float s_p [8][FF];
    __shared__ float s_d [4][2][8];
    __shared__ float s_out[MMM];

    for (int t = 0; t < FF; t++){
        for (int l = 0; l < LLAY; l++){
            // ==== Stage A: layer input (LN3 fused for l>0, from shared) + qkv ====
            if (l == 0){
                for (int j = tid; j < BB*DD/4; j += 256)
                    ((float4*)s_x)[j] = ld_cg4(g_xb + j*4);
            } else {
                const float4* lng = (const float4*)(ln_g + ((size_t)(l-1)*3 + 2)*DD);
                const float4* lnb = (const float4*)(ln_b + ((size_t)(l-1)*3 + 2)*DD);
                int b = w;
                float4 v[4]; float s = 0.f;
#pragma unroll
                for (int q = 0; q < 4; q++){
                    int i = lane + q*32;
                    float4 a = ((const float4*)s_x[b])[i];          // x2 from stage C
                    float4 y = ld_cg4(g_y + b*DD + i*4);
                    v[q].x = a.x+y.x; v[q].y = a.y+y.y; v[q].z = a.z+y.z; v[q].w = a.w+y.w;
                    s += v[q].x+v[q].y+v[q].z+v[q].w;
                }
                s = warp_sum(s); float mu = s * (1.f/DD);
                float vs = 0.f;
#pragma unroll
                for (int q = 0; q < 4; q++){
                    float dx=v[q].x-mu, dy=v[q].y-mu, dz=v[q].z-mu, dw=v[q].w-mu;
                    vs += dx*dx+dy*dy+dz*dz+dw*dw;
                }
                vs = warp_sum(vs); float rstd = rsqrtf(vs*(1.f/DD) + LNEPS);
#pragma unroll
                for (int q = 0; q < 4; q++){
                    int i = lane + q*32;
                    float4 gg = lng[i], bb = lnb[i], o;
                    o.x = (v[q].x-mu)*rstd*gg.x + bb.x;
                    o.y = (v[q].y-mu)*rstd*gg.y + bb.y;
                    o.z = (v[q].z-mu)*rstd*gg.z + bb.z;
                    o.w = (v[q].w-mu)*rstd*gg.w + bb.w;
                    ((float4*)s_x[b])[i] = o;
                }
            }
            __syncthreads();
            {
                const float* Wq = sa_in_w + (size_t)l*3*DD*DD;
                const float* bq = sa_in_b + (size_t)l*3*DD;
                for (int rr = gw; rr < 3*DD; rr += NWARP){
                    const float4* w4 = (const float4*)(Wq + (size_t)rr*DD);
                    float acc[8] = {0.f,0.f,0.f,0.f,0.f,0.f,0.f,0.f};
#pragma unroll
                    for (int q = 0; q < 4; q++){
                        int i = lane + q*32;
                        float4 wv = w4[i];
#pragma unroll
                        for (int b = 0; b < 8; b++)
                            acc[b] += dot4(wv, ((const float4*)s_x[b])[i]);
                    }
#pragma unroll
                    for (int o = 16; o; o >>= 1){
#pragma unroll
                        for (int b = 0; b < 8; b++) acc[b] += __shfl_xor_sync(0xffffffffu, acc[b], o);
                    }
                    float bv = bq[rr];
#pragma unroll
                    for (int b = 0; b < 8; b++){
                        if (lane == b){
                            float val = acc[b] + bv;
                            if (rr < DD)        g_q[b*DD + rr] = val;
                            else if (rr < 2*DD) g_K[(((size_t)l*BB + b)*FF + t)*DD + (rr - DD)]   = val;
                            else                g_V[(((size_t)l*BB + b)*FF + t)*DD + (rr - 2*DD)] = val;
                        }
                    }
                }
            }
            grid_sync(phase);

            // ==== Stage B: attention (8 warps = 8 heads, batch myb) + out-proj ====
            {
                int h = w;
                if (lane < 16) ((float4*)s_qb[w])[lane] = ld_cg4(g_q + myb*DD + h*DHH + lane*4);
                __syncwarp();
                const float* Kb = g_K + (((size_t)l*BB + myb)*FF)*DD + h*DHH;
                const float* Vb = g_V + (((size_t)l*BB + myb)*FF)*DD + h*DHH;
                float slope = exp2f(-(float)(h + 1));
                int j0 = lane, j1 = lane + 32;
                float sc0 = -1e30f, sc1 = -1e30f;
                if (j0 <= t){
                    const float4* kr = (const float4*)(Kb + (size_t)j0*DD);
                    float a = 0.f;
#pragma unroll
                    for (int i = 0; i < 16; i++) a += dot4(((const float4*)s_qb[w])[i], kr[i]);
                    sc0 = a*0.125f - slope * (float)((t - j0)/30);
                }
                if (j1 <= t){
                    const float4* kr = (const float4*)(Kb + (size_t)j1*DD);
                    float a = 0.f;
#pragma unroll
                    for (int i = 0; i < 16; i++) a += dot4(((const float4*)s_qb[w])[i], kr[i]);
                    sc1 = a*0.125f - slope * (float)((t - j1)/30);
                }
                float m = fmaxf(sc0, sc1);
#pragma unroll
                for (int o = 16; o; o >>= 1) m = fmaxf(m, __shfl_xor_sync(0xffffffffu, m, o));
                float e0 = (j0 <= t) ? expf(sc0 - m) : 0.f;
                float e1 = (j1 <= t) ? expf(sc1 - m) : 0.f;
                float sm = warp_sum(e0 + e1);
                float inv = 1.f / sm;
                s_p[w][j0] = e0 * inv;
                if (j1 < FF) s_p[w][j1] = e1 * inv;
                __syncwarp();
#pragma unroll
                for (int dq = 0; dq < 2; dq++){
                    int d = lane + dq*32;
                    float a = 0.f;
#pragma unroll 4
                    for (int j = 0; j <= t; j++) a += s_p[w][j] * Vb[(size_t)j*DD + d];
                    s_attn[h*DHH + d] = a;
                }
            }
            __syncthreads();
            {
                const float* Wo = sa_out_w + (size_t)l*DD*DD;
                const float* bo = sa_out_b + (size_t)l*DD;
                float4 av[4];
#pragma unroll
                for (int q = 0; q < 4; q++) av[q] = ((const float4*)s_attn)[lane + q*32];
#pragma unroll
                for (int uq = 0; uq < 4; uq++){
                    int d = sub*32 + w*4 + uq;
                    const float4* w4 = (const float4*)(Wo + (size_t)d*DD);
                    float a = 0.f;
#pragma unroll
                    for (int q = 0; q < 4; q++) a += dot4(av[q], w4[lane + q*32]);
                    a = warp_sum(a);
                    if (lane == 0) g_r[myb*DD + d] = a + bo[d] + s_x[myb][d];
                }
            }
            grid_sync(phase);

            // ==== Stage C: LN1 + XA + LN2 (warp b per batch) then ff1 ====
            {
                const float4* lng1 = (const float4*)(ln_g + ((size_t)l*3 + 0)*DD);
                const float4* lnb1 = (const float4*)(ln_b + ((size_t)l*3 + 0)*DD);
                const float4* lng2 = (const float4*)(ln_g + ((size_t)l*3 + 1)*DD);
                const float4* lnb2 = (const float4*)(ln_b + ((size_t)l*3 + 1)*DD);
                int b = w;
                const float4* xa4 = (const float4*)(g_XA + (((size_t)l*BB + b)*FF + t)*DD);
                float4 v[4]; float s = 0.f;
#pragma unroll
                for (int q = 0; q < 4; q++){
                    int i = lane + q*32;
                    v[q] = ld_cg4(g_r + b*DD + i*4);
                    s += v[q].x+v[q].y+v[q].z+v[q].w;
                }
                s = warp_sum(s); float mu = s * (1.f/DD);
                float vs = 0.f;
#pragma unroll
                for (int q = 0; q < 4; q++){
                    float dx=v[q].x-mu, dy=v[q].y-mu, dz=v[q].z-mu, dw=v[q].w-mu;
                    vs += dx*dx+dy*dy+dz*dz+dw*dw;
                }
                vs = warp_sum(vs); float rstd = rsqrtf(vs*(1.f/DD) + LNEPS);
                float s2 = 0.f;
#pragma unroll
                for (int q = 0; q < 4; q++){
                    int i = lane + q*32;
                    float4 gg = lng1[i], bb = lnb1[i], xa = xa4[i], r2;
                    r2.x = (v[q].x-mu)*rstd*gg.x + bb.x + xa.x;
                    r2.y = (v[q].y-mu)*rstd*gg.y + bb.y + xa.y;
                    r2.z = (v[q].z-mu)*rstd*gg.z + bb.z + xa.z;
                    r2.w = (v[q].w-mu)*rstd*gg.w + bb.w + xa.w;
                    v[q] = r2; s2 += r2.x+r2.y+r2.z+r2.w;
                }
                s2 = warp_sum(s2); mu = s2 * (1.f/DD);
                vs = 0.f;
#pragma unroll
                for (int q = 0; q < 4; q++){
                    float dx=v[q].x-mu, dy=v[q].y-mu, dz=v[q].z-mu, dw=v[q].w-mu;
                    vs += dx*dx+dy*dy+dz*dz+dw*dw;
                }
                vs = warp_sum(vs); rstd = rsqrtf(vs*(1.f/DD) + LNEPS);
#pragma unroll
                for (int q = 0; q < 4; q++){
                    int i = lane + q*32;
                    float4 gg = lng2[i], bb = lnb2[i], o;
                    o.x = (v[q].x-mu)*rstd*gg.x + bb.x;
                    o.y = (v[q].y-mu)*rstd*gg.y + bb.y;
                    o.z = (v[q].z-mu)*rstd*gg.z + bb.z;
                    o.w = (v[q].w-mu)*rstd*gg.w + bb.w;
                    ((float4*)s_x[b])[i] = o;
                }
            }
            __syncthreads();
            {
                const float* W1 = ff1_w + (size_t)l*DFFF*DD;
                const float* b1 = ff1_b + (size_t)l*DFFF;
                for (int rr = gw; rr < DFFF; rr += NWARP){
                    const float4* w4 = (const float4*)(W1 + (size_t)rr*DD);
                    float acc[8] = {0.f,0.f,0.f,0.f,0.f,0.f,0.f,0.f};
#pragma unroll
                    for (int q = 0; q < 4; q++){
                        int i = lane + q*32;
                        float4 wv = w4[i];
#pragma unroll
                        for (int b = 0; b < 8; b++)
                            acc[b] += dot4(wv, ((const float4*)s_x[b])[i]);
                    }
#pragma unroll
                    for (int o = 16; o; o >>= 1){
#pragma unroll
                        for (int b = 0; b < 8; b++) acc[b] += __shfl_xor_sync(0xffffffffu, acc[b], o);
                    }
                    float bv = b1[rr];
#pragma unroll
                    for (int b = 0; b < 8; b++)
                        if (lane == b) g_h[b*DFFF + rr] = fmaxf(acc[b] + bv, 0.f);
                }
            }
            grid_sync(phase);

            // ==== Stage D: ff2 (split-K: 2 warps per output row) ====
            {
                int rloc = w >> 1, half = w & 1;
                int rr = blockIdx.x * 4 + rloc;
                const float4* w4 = (const float4*)(ff2_w + (size_t)l*DD*DFFF + (size_t)rr*DFFF + half*1024);
                const float* hh = g_h + half*1024;
                float acc[8] = {0.f,0.f,0.f,0.f,0.f,0.f,0.f,0.f};
#pragma unroll
                for (int q = 0; q < 8; q++){
                    int i = lane + q*32;
                    float4 wv = w4[i];
#pragma unroll
                    for (int b = 0; b < 8; b++)
                        acc[b] += dot4(wv, ld_cg4(hh + (size_t)b*DFFF + i*4));
                }
#pragma unroll
                for (int o = 16; o; o >>= 1){
#pragma unroll
                    for (int b = 0; b < 8; b++) acc[b] += __shfl_xor_sync(0xffffffffu, acc[b], o);
                }
                if (lane < 8) s_d[rloc][half][lane] = acc[lane];
                __syncthreads();
                if (w < 4 && lane < 8){
                    int r2 = blockIdx.x * 4 + w;
                    g_y[lane*DD + r2] = s_d[w][0][lane] + s_d[w][1][lane] + ff2_b[(size_t)l*DD + r2];
                }
            }
            grid_sync(phase);
        } // layers

        // ==== Stage H: LN3 + head (batch myb, warp-redundant LN) + next emb ====
        {
            const float4* lng3 = (const float4*)(ln_g + (size_t)((LLAY-1)*3 + 2)*DD);
            const float4* lnb3 = (const float4*)(ln_b + (size_t)((LLAY-1)*3 + 2)*DD);
            float4 x3[4]; float s = 0.f;
#pragma unroll
            for (int q = 0; q < 4; q++){
                int i = lane + q*32;
                float4 a = ((const float4*)s_x[myb])[i];
                float4 y = ld_cg4(g_y + myb*DD + i*4);
                x3[q].x = a.x+y.x; x3[q].y = a.y+y.y; x3[q].z = a.z+y.z; x3[q].w = a.w+y.w;
                s += x3[q].x+x3[q].y+x3[q].z+x3[q].w;
            }
            s = warp_sum(s); float mu = s * (1.f/DD);
            float vs = 0.f;
#pragma unroll
            for (int q = 0; q < 4; q++){
                float dx=x3[q].x-mu, dy=x3[q].y-mu, dz=x3[q].z-mu, dw=x3[q].w-mu;
                vs += dx*dx+dy*dy+dz*dz+dw*dw;
            }
            vs = warp_sum(vs); float rstd = rsqrtf(vs*(1.f/DD) + LNEPS);
#pragma unroll
            for (int q = 0; q < 4; q++){
                int i = lane + q*32;
                float4 gg = lng3[i], bb = lnb3[i];
                x3[q].x = (x3[q].x-mu)*rstd*gg.x + bb.x;
                x3[q].y = (x3[q].y-mu)*rstd*gg.y + bb.y;
                x3[q].z = (x3[q].z-mu)*rstd*gg.z + bb.z;
                x3[q].w = (x3[q].w-mu)*rstd*gg.w + bb.w;
            }
#pragma unroll
            for (int jj = 0; jj < 8; jj++){
                int j = w*8 + jj;
                const float4* w4 = (const float4*)(mmr_w + (size_t)j*DD);
                float a = 0.f;
#pragma unroll
                for (int q = 0; q < 4; q++) a += dot4(x3[q], w4[lane + q*32]);
                a = warp_sum(a);
                if (lane == 0){
                    float val = a + mmr_b[j];
                    s_out[j] = val;
                    dec_out[((size_t)myb*FF + t)*MMM + j] = val;   // redundant same-value writes
                }
            }
        }
        __syncthreads();
        if (t < FF - 1){
            float o0 = s_out[lane], o1 = s_out[lane + 32];
#pragma unroll
            for (int uq = 0; uq < 4; uq++){
                int d = sub*32 + w*4 + uq;
                const float* cw = g_CW + (size_t)d*MMM;
                float a = o0*cw[lane] + o1*cw[lane + 32];
                a = warp_sum(a);
                if (lane == 0)
                    g_xb[myb*DD + d] = a + g_cb[d] + g_E2[((size_t)myb*FF + t + 1)*DD + d];
            }
            grid_sync(phase);
        }
    } // steps
}

// ---------------- launch ---------------------------------------------------------
extern "C" void kernel_launch(void* const* d_in, const int* in_sizes, int n_in,
                              void* d_out, int out_size){
    const float* content       = (const float*)d_in[0];
    const float* style_code    = (const float*)d_in[1];
    const float* style_hiddens = (const float*)d_in[2];
    const float* init_state    = (const float*)d_in[3];
    const float* ca_in_w  = (const float*)d_in[4];
    const float* ca_in_b  = (const float*)d_in[5];
    const float* ca_out_w = (const float*)d_in[6];
    const float* ca_out_b = (const float*)d_in[7];
    const float* se_w     = (const float*)d_in[8];
    const float* se_b     = (const float*)d_in[9];
    const float* mm_w     = (const float*)d_in[10];
    const float* mm_b     = (const float*)d_in[11];
    const float* mmr_w    = (const float*)d_in[12];
    const float* mmr_b    = (const float*)d_in[13];
    const float* sa_in_w  = (const float*)d_in[14];
    const float* sa_in_b  = (const float*)d_in[15];
    const float* sa_out_w = (const float*)d_in[16];
    const float* sa_out_b = (const float*)d_in[17];
    const float* xa_in_w  = (const float*)d_in[18];
    const float* xa_in_b  = (const float*)d_in[19];
    const float* xa_out_w = (const float*)d_in[20];
    const float* xa_out_b = (const float*)d_in[21];
    const float* ff1_w    = (const float*)d_in[22];
    const float* ff1_b    = (const float*)d_in[23];
    const float* ff2_w    = (const float*)d_in[24];
    const float* ff2_b    = (const float*)d_in[25];
    const float* ln_g     = (const float*)d_in[26];
    const float* ln_b     = (const float*)d_in[27];

    float* dec_out = (float*)d_out;                      // (B,48,64)
    float* sel     = (float*)d_out + BB*FF*MMM;          // (B,48,512)

    dim3 blk(256);

    // 1) CA in-proj (q/k/v)
    ca_inproj_kernel<<<dim3(64, 64, 3), blk>>>(content, style_hiddens, ca_in_w, ca_in_b);
    // 2) sel attention (in-place on g_qh)
    ca_attn_kernel<<<BB*FF, 256>>>();
    // 3) sel out-proj + XA value-proj (z-fused)
    fused3_kernel<<<dim3(64, 48, 5), blk>>>(content, ca_out_w, ca_out_b, xa_in_w, xa_in_b, sel);
    // 4) XA out-proj
    xa2_kernel<<<dim3(64, 48, LLAY), blk>>>(xa_out_w, xa_out_b);
    // 5) E2 + CW fold + x0 + barrier reset
    misc_kernel<<<3593, 256>>>(sel, se_w, se_b, style_code, mm_w, mm_b, init_state);
    // 6) persistent autoregressive decode (profiled slot)
    decode_kernel<<<GRID, 256>>>(sa_in_w, sa_in_b, sa_out_w, sa_out_b,
                                 ff1_w, ff1_b, ff2_w, ff2_b,
                                 ln_g, ln_b, mmr_w, mmr_b, dec_out);
}

// round 16
// speedup vs baseline: 1.2138x; 1.2138x over previous
#include <cuda_runtime.h>
#include <cstdint>
#include <math.h>

#define BB   8
#define FF   48
#define SS   64
#define DD   512
#define NHH  8
#define DHH  64
#define LLAY 4
#define DFFF 2048
#define MMM  64
#define LNEPS 1e-5f
#define GRID 128          // persistent blocks (<= SM count -> all co-resident)
#define NWARP (GRID*8)    // 1024 warps

// ---------------- scratch (device globals; allocation-free) ----------------
__device__ __align__(16) float g_q   [BB*DD];
__device__ __align__(16) float g_xb  [BB*DD];
__device__ __align__(16) float g_y   [BB*DD];
__device__ __align__(16) float g_r   [BB*DD];
__device__ __align__(16) float g_h   [BB*DFFF];
__device__ __align__(16) float g_K   [LLAY*BB*FF*DD];
__device__ __align__(16) float g_V   [LLAY*BB*FF*DD];
__device__ __align__(16) float g_XA  [LLAY*BB*FF*DD];
__device__ __align__(16) float g_E2  [BB*FF*DD];
__device__ __align__(16) float g_CW  [DD*MMM];
__device__ __align__(16) float g_cb  [DD];
__device__ __align__(16) float g_qh  [BB*FF*DD];
__device__ __align__(16) float g_kh  [BB*SS*DD];
__device__ __align__(16) float g_vh  [BB*SS*DD];
__device__ __align__(16) float g_tmpL[LLAY*BB*FF*DD];

// tree barrier state: 8 group counters (own lines) + root + generation
__device__ __align__(128) unsigned g_gcnt[8*32];
__device__ __align__(128) unsigned g_root[32];
__device__ __align__(128) unsigned g_gen1[32];

// ---------------- helpers ----------------
__device__ __forceinline__ float warp_sum(float v){
#pragma unroll
    for (int o = 16; o; o >>= 1) v += __shfl_xor_sync(0xffffffffu, v, o);
    return v;
}
__device__ __forceinline__ float dot4(float4 a, float4 b){
    return a.x*b.x + a.y*b.y + a.z*b.z + a.w*b.w;
}
__device__ __forceinline__ void cp16(unsigned int sa, const float* g){
    asm volatile("cp.async.cg.shared.global [%0], [%1], 16;" :: "r"(sa), "l"(g));
}
__device__ __forceinline__ void cp_commit(){ asm volatile("cp.async.commit_group;" ::: "memory"); }
__device__ __forceinline__ void cp_wait(){ asm volatile("cp.async.wait_group 0;" ::: "memory"); }

__device__ __forceinline__ void pf_row512(float* sdst, const float* gsrc, int lane){
    unsigned int sa = (unsigned int)__cvta_generic_to_shared(sdst);
#pragma unroll
    for (int c = 0; c < 4; c++)
        cp16(sa + (lane + c*32)*16, gsrc + (lane + c*32)*4);
}
__device__ __forceinline__ void pf_row1024(float* sdst, const float* gsrc, int lane){
    unsigned int sa = (unsigned int)__cvta_generic_to_shared(sdst);
#pragma unroll
    for (int c = 0; c < 8; c++)
        cp16(sa + (lane + c*32)*16, gsrc + (lane + c*32)*4);
}

// two-level tree barrier; monotonic counters, phase tracked per-thread (R12-proven)
__device__ __forceinline__ void grid_sync(unsigned &phase, int grp){
    __syncthreads();
    if (threadIdx.x == 0){
        unsigned p;
        asm volatile("atom.add.acq_rel.gpu.u32 %0, [%1], 1;"
                     : "=r"(p) : "l"(&g_gcnt[grp*32]) : "memory");
        if (p == phase*16u + 15u){
            unsigned q;
            asm volatile("atom.add.acq_rel.gpu.u32 %0, [%1], 1;"
                         : "=r"(q) : "l"(g_root) : "memory");
            if (q == phase*8u + 7u){
                asm volatile("st.release.gpu.u32 [%0], %1;"
                             :: "l"(g_gen1), "r"(phase + 1u) : "memory");
            }
        }
        unsigned cur;
        do {
            asm volatile("ld.acquire.gpu.u32 %0, [%1];" : "=r"(cur) : "l"(g_gen1) : "memory");
        } while (cur <= phase);
    }
    phase++;
    __syncthreads();
}

// ================= precompute kernels (5 launches before decode) =================

// launch 1: CA in-proj. z=0 q(content,384 rows), z=1 k(style,512), z=2 v(style,512)
__global__ void ca_inproj_kernel(const float* __restrict__ content, const float* __restrict__ style,
                                 const float* __restrict__ ca_in_w, const float* __restrict__ ca_in_b){
    int z = blockIdx.z;
    const float* X = (z == 0) ? content : style;
    int R = (z == 0) ? BB*FF : BB*SS;
    float* out = (z == 0) ? g_qh : (z == 1 ? g_kh : g_vh);
    const float* W = ca_in_w + (size_t)z*DD*DD;
    const float* bias = ca_in_b + z*DD;
    int warp = threadIdx.x >> 5, lane = threadIdx.x & 31;
    int n  = blockIdx.x * 8 + warp;
    int r0 = blockIdx.y * 8;
    if (r0 >= R) return;
    const float4* w4 = (const float4*)(W + (size_t)n * DD);
    const float* x = X + (size_t)r0 * DD;
    float acc[8] = {0.f,0.f,0.f,0.f,0.f,0.f,0.f,0.f};
#pragma unroll
    for (int q = 0; q < 4; q++){
        int i = lane + q*32;
        float4 wv = w4[i];
#pragma unroll
        for (int b = 0; b < 8; b++)
            acc[b] += dot4(wv, ((const float4*)(x + (size_t)b*DD))[i]);
    }
#pragma unroll
    for (int o = 16; o; o >>= 1){
#pragma unroll
        for (int b = 0; b < 8; b++) acc[b] += __shfl_xor_sync(0xffffffffu, acc[b], o);
    }
    float bv = bias[n];
#pragma unroll
    for (int b = 0; b < 8; b++)
        if (lane == b) out[(size_t)(r0 + b) * DD + n] = acc[b] + bv;
}

// launch 2: sel attention (nh=1, softmax over S=64), IN-PLACE on g_qh
__global__ void ca_attn_kernel(){
    int r = blockIdx.x;
    int b = r / FF;
    __shared__ __align__(16) float s_q[DD];
    __shared__ float s_p[SS];
    int tid = threadIdx.x, warp = tid >> 5, lane = tid & 31;
    for (int d = tid; d < DD; d += 256) s_q[d] = g_qh[(size_t)r*DD + d];
    __syncthreads();
    for (int s = warp; s < SS; s += 8){
        const float4* kr4 = (const float4*)(g_kh + (size_t)(b*SS + s)*DD);
        float a = 0.f;
#pragma unroll
        for (int q = 0; q < 4; q++){
            int i = lane + q*32;
            a += dot4(((const float4*)s_q)[i], kr4[i]);
        }
        a = warp_sum(a);
        if (lane == 0) s_p[s] = a * 0.04419417382415922f;
    }
    __syncthreads();
    if (warp == 0){
        float v0 = s_p[lane], v1 = s_p[lane + 32];
        float m = fmaxf(v0, v1);
#pragma unroll
        for (int o2 = 16; o2; o2 >>= 1) m = fmaxf(m, __shfl_xor_sync(0xffffffffu, m, o2));
        float e0 = expf(v0 - m), e1 = expf(v1 - m);
        float sm = warp_sum(e0 + e1);
        float inv = 1.f / sm;
        s_p[lane] = e0 * inv; s_p[lane + 32] = e1 * inv;
    }
    __syncthreads();
    for (int d = tid; d < DD; d += 256){
        float a = 0.f;
#pragma unroll 8
        for (int s = 0; s < SS; s++) a += s_p[s] * g_vh[(size_t)(b*SS + s)*DD + d];
        g_qh[(size_t)r*DD + d] = a;
    }
}

// launch 3: z=0 sel = g_qh @ ca_out; z=1..4: tmpL[l] = content @ xa_v[l]
__global__ void fused3_kernel(const float* __restrict__ content,
                              const float* __restrict__ ca_out_w, const float* __restrict__ ca_out_b,
                              const float* __restrict__ xa_in_w,  const float* __restrict__ xa_in_b,
                              float* __restrict__ sel){
    int z = blockIdx.z;
    const float *X, *W, *bias; float* out;
    if (z == 0){ X = g_qh; W = ca_out_w; bias = ca_out_b; out = sel; }
    else {
        int l = z - 1;
        X = content;
        W = xa_in_w + (size_t)l*3*DD*DD + 2*DD*DD;
        bias = xa_in_b + (size_t)l*3*DD + 2*DD;
        out = g_tmpL + (size_t)l*BB*FF*DD;
    }
    int warp = threadIdx.x >> 5, lane = threadIdx.x & 31;
    int n  = blockIdx.x * 8 + warp;
    int r0 = blockIdx.y * 8;
    const float4* w4 = (const float4*)(W + (size_t)n * DD);
    const float* x = X + (size_t)r0 * DD;
    float acc[8] = {0.f,0.f,0.f,0.f,0.f,0.f,0.f,0.f};
#pragma unroll
    for (int q = 0; q < 4; q++){
        int i = lane + q*32;
        float4 wv = w4[i];
#pragma unroll
        for (int b = 0; b < 8; b++)
            acc[b] += dot4(wv, ((const float4*)(x + (size_t)b*DD))[i]);
    }
#pragma unroll
    for (int o = 16; o; o >>= 1){
#pragma unroll
        for (int b = 0; b < 8; b++) acc[b] += __shfl_xor_sync(0xffffffffu, acc[b], o);
    }
    float bv = bias[n];
#pragma unroll
    for (int b = 0; b < 8; b++)
        if (lane == b) out[(size_t)(r0 + b) * DD + n] = acc[b] + bv;
}

// launch 4: XA[l] = tmpL[l] @ xa_out[l]
__global__ void xa2_kernel(const float* __restrict__ xa_out_w, const float* __restrict__ xa_out_b){
    int z = blockIdx.z;
    const float* X = g_tmpL + (size_t)z*BB*FF*DD;
    const float* W = xa_out_w + (size_t)z*DD*DD;
    const float* bias = xa_out_b + (size_t)z*DD;
    float* out = g_XA + (size_t)z*BB*FF*DD;
    int warp = threadIdx.x >> 5, lane = threadIdx.x & 31;
    int n  = blockIdx.x * 8 + warp;
    int r0 = blockIdx.y * 8;
    const float4* w4 = (const float4*)(W + (size_t)n * DD);
    const float* x = X + (size_t)r0 * DD;
    float acc[8] = {0.f,0.f,0.f,0.f,0.f,0.f,0.f,0.f};
#pragma unroll
    for (int q = 0; q < 4; q++){
        int i = lane + q*32;
        float4 wv = w4[i];
#pragma unroll
        for (int b = 0; b < 8; b++)
            acc[b] += dot4(wv, ((const float4*)(x + (size_t)b*DD))[i]);
    }
#pragma unroll
    for (int o = 16; o; o >>= 1){
#pragma unroll
        for (int b = 0; b < 8; b++) acc[b] += __shfl_xor_sync(0xffffffffu, acc[b], o);
    }
    float bv = bias[n];
#pragma unroll
    for (int b = 0; b < 8; b++)
        if (lane == b) out[(size_t)(r0 + b) * DD + n] = acc[b] + bv;
}

// launch 5: misc — e2 (3072 blocks) + CW fold (512) + x0 init (8) + barrier reset (1)
__global__ void misc_kernel(const float* __restrict__ sel, const float* __restrict__ se_w,
                            const float* __restrict__ se_b, const float* __restrict__ style,
                            const float* __restrict__ mm_w, const float* __restrict__ mm_b,
                            const float* __restrict__ init_state){
    int bid = blockIdx.x, tid = threadIdx.x;
    if (bid < 3072){
        int bx = bid & 63, by = bid >> 6;
        int warp = tid >> 5, lane = tid & 31;
        int n  = bx * 8 + warp;
        int r0 = by * 8;
        int b  = r0 / FF;
        const float4* w4 = (const float4*)(se_w + (size_t)n * 1024 + 512);
        const float4* xr[8];
#pragma unroll
        for (int q = 0; q < 8; q++){
            int p  = (r0 + q) % FF;
            int ip = p ? (p - 1) : 0;
            xr[q] = (const float4*)(sel + ((size_t)b*FF + ip)*DD);
        }
        float acc[8] = {0.f,0.f,0.f,0.f,0.f,0.f,0.f,0.f};
#pragma unroll
        for (int i4 = 0; i4 < 4; i4++){
            int i = lane + i4*32;
            float4 wv = w4[i];
#pragma unroll
            for (int q = 0; q < 8; q++) acc[q] += dot4(wv, xr[q][i]);
        }
#pragma unroll
        for (int o = 16; o; o >>= 1){
#pragma unroll
            for (int q = 0; q < 8; q++) acc[q] += __shfl_xor_sync(0xffffffffu, acc[q], o);
        }
#pragma unroll
        for (int q = 0; q < 8; q++){
            if (lane == q){
                int p = (r0 + q) % FF;
                float pos = (float)(p % 30);
                const float LF = 9.210340371976184f / 512.f;
                float pe;
                if (n & 1) pe = cosf(pos * expf(-(float)(n - 1) * LF));
                else       pe = sinf(pos * expf(-(float)n       * LF));
                g_E2[((size_t)r0 + q)*DD + n] = acc[q] + se_b[n] + style[b*DD + n] + pe;
            }
        }
    } else if (bid < 3584){
        int d = bid - 3072;
        __shared__ float s_w1[DD];
        for (int k = tid; k < DD; k += 256) s_w1[k] = se_w[(size_t)d*1024 + k];
        __syncthreads();
        if (tid < 64){
            int j = tid;
            float a = 0.f;
            for (int k = 0; k < DD; k++) a += s_w1[k] * mm_w[(size_t)k*MMM + j];
            g_CW[(size_t)d*MMM + j] = a;
            if (j == 0){
                float c = 0.f;
                for (int k = 0; k < DD; k++) c += s_w1[k] * mm_b[k];
                g_cb[d] = c;
            }
        }
    } else if (bid < 3592){
        int b = bid - 3584;
        __shared__ __align__(16) float s_feat[DD];
        for (int d = tid; d < DD; d += 256){
            float a = mm_b[d];
            const float* mw = mm_w + (size_t)d * MMM;
            const float* is = init_state + b * MMM;
#pragma unroll
            for (int k = 0; k < MMM; k++) a += is[k] * mw[k];
            s_feat[d] = a;
        }
        __syncthreads();
        for (int d = tid; d < DD; d += 256){
            const float4* w1 = (const float4*)(se_w + (size_t)d * 1024);
            const float4* w2 = (const float4*)(se_w + (size_t)d * 1024 + 512);
            const float4* s0 = (const float4*)(sel + (size_t)b*FF*DD);
            float a1 = 0.f, a2 = 0.f;
#pragma unroll
            for (int i = 0; i < 128; i++){
                a1 += dot4(((const float4*)s_feat)[i], w1[i]);
                a2 += dot4(s0[i], w2[i]);
            }
            float pe = (d & 1) ? 1.f : 0.f;   // PE[0]: sin(0)=0 (even), cos(0)=1 (odd)
            g_xb[b*DD + d] = a1 + a2 + se_b[d] + style[b*DD + d] + pe;
        }
    } else {
        if (tid < 8) g_gcnt[tid*32] = 0;
        if (tid == 8) g_root[0] = 0;
        if (tid == 9) g_gen1[0] = 0;
    }
}

// ================= persistent decode kernel (R12 structure + cp.async prefetch) =
__global__ void __launch_bounds__(256, 1) decode_kernel(
    const float* __restrict__ sa_in_w,  const float* __restrict__ sa_in_b,
    const float* __restrict__ sa_out_w, const float* __restrict__ sa_out_b,
    const float* __restrict__ ff1_w,    const float* __restrict__ ff1_b,
    const float* __restrict__ ff2_w,    const float* __restrict__ ff2_b,
    const float* __restrict__ ln_g,     const float* __restrict__ ln_b,
    const float* __restrict__ mmr_w,    const float* __restrict__ mmr_b,
    float* __restrict__ dec_out)
{
    extern __shared__ __align__(16) float s_wst[];   // 16384 floats = 64KB staging
    int tid = threadIdx.x, w = tid >> 5, lane = tid & 31;
    int gw  = blockIdx.x * 8 + w;
    int myb = blockIdx.x >> 4;
    int sub = blockIdx.x & 15;
    int grp = blockIdx.x >> 4;
    unsigned phase = 0;
    float* swp = s_wst + w*2048;       // per-warp 8KB staging slice
    __shared__ __align__(16) float s_x [BB][DD];
    __shared__ __align__(16) float s_attn[DD];
    __shared__ __align__(16) float s_qb[8][DHH];
    __shared__ float s_p [8][FF];
    __shared__ float s_d [4][2][8];
    __shared__ float s_out[MMM];

    // initial prefetch: qkv weights for (t=0, l=0)
    {
        pf_row512(swp, sa_in_w + (size_t)gw*DD, lane);
        if (gw < 512) pf_row512(swp + 512, sa_in_w + (size_t)(gw+1024)*DD, lane);
        cp_commit();
    }

    for (int t = 0; t < FF; t++){
        for (int l = 0; l < LLAY; l++){
            // ==== Stage A: layer input (LN3 fused for l>0) + qkv from staged weights ====
            if (l == 0){
                for (int j = tid; j < BB*DD/4; j += 256)
                    ((float4*)s_x)[j] = ((const float4*)g_xb)[j];
            } else {
                const float4* lng = (const float4*)(ln_g + ((size_t)(l-1)*3 + 2)*DD);
                const float4* lnb = (const float4*)(ln_b + ((size_t)(l-1)*3 + 2)*DD);
                int b = w;
                float4 v[4]; float s = 0.f;
#pragma unroll
                for (int q = 0; q < 4; q++){
                    int i = lane + q*32;
                    float4 a = ((const float4*)s_x[b])[i];          // x2 from stage C
                    float4 y = ((const float4*)(g_y + b*DD))[i];
                    v[q].x = a.x+y.x; v[q].y = a.y+y.y; v[q].z = a.z+y.z; v[q].w = a.w+y.w;
                    s += v[q].x+v[q].y+v[q].z+v[q].w;
                }
                s = warp_sum(s); float mu = s * (1.f/DD);
                float vs = 0.f;
#pragma unroll
                for (int q = 0; q < 4; q++){
                    float dx=v[q].x-mu, dy=v[q].y-mu, dz=v[q].z-mu, dw=v[q].w-mu;
                    vs += dx*dx+dy*dy+dz*dz+dw*dw;
                }
                vs = warp_sum(vs); float rstd = rsqrtf(vs*(1.f/DD) + LNEPS);
#pragma unroll
                for (int q = 0; q < 4; q++){
                    int i = lane + q*32;
                    float4 gg = lng[i], bb = lnb[i], o;
                    o.x = (v[q].x-mu)*rstd*gg.x + bb.x;
                    o.y = (v[q].y-mu)*rstd*gg.y + bb.y;
                    o.z = (v[q].z-mu)*rstd*gg.z + bb.z;
                    o.w = (v[q].w-mu)*rstd*gg.w + bb.w;
                    ((float4*)s_x[b])[i] = o;
                }
            }
            __syncthreads();
            {
                const float* bq = sa_in_b + (size_t)l*3*DD;
                cp_wait(); __syncwarp();
                // row 1: rr = gw  (q if gw<512, else K)
                {
                    const float4* w4 = (const float4*)swp;
                    float acc[8] = {0.f,0.f,0.f,0.f,0.f,0.f,0.f,0.f};
#pragma unroll
                    for (int q = 0; q < 4; q++){
                        int i = lane + q*32;
                        float4 wv = w4[i];
#pragma unroll
                        for (int b = 0; b < 8; b++)
                            acc[b] += dot4(wv, ((const float4*)s_x[b])[i]);
                    }
#pragma unroll
                    for (int o = 16; o; o >>= 1){
#pragma unroll
                        for (int b = 0; b < 8; b++) acc[b] += __shfl_xor_sync(0xffffffffu, acc[b], o);
                    }
                    float bv = bq[gw];
#pragma unroll
                    for (int b = 0; b < 8; b++){
                        if (lane == b){
                            float val = acc[b] + bv;
                            if (gw < DD) g_q[b*DD + gw] = val;
                            else         g_K[(((size_t)l*BB + b)*FF + t)*DD + (gw - DD)] = val;
                        }
                    }
                }
                // row 2: rr = gw + 1024 (always V), only for gw < 512
                if (gw < 512){
                    const float4* w4 = (const float4*)(swp + 512);
                    float acc[8] = {0.f,0.f,0.f,0.f,0.f,0.f,0.f,0.f};
#pragma unroll
                    for (int q = 0; q < 4; q++){
                        int i = lane + q*32;
                        float4 wv = w4[i];
#pragma unroll
                        for (int b = 0; b < 8; b++)
                            acc[b] += dot4(wv, ((const float4*)s_x[b])[i]);
                    }
#pragma unroll
                    for (int o = 16; o; o >>= 1){
#pragma unroll
                        for (int b = 0; b < 8; b++) acc[b] += __shfl_xor_sync(0xffffffffu, acc[b], o);
                    }
                    float bv = bq[gw + 1024];
#pragma unroll
                    for (int b = 0; b < 8; b++)
                        if (lane == b) g_V[(((size_t)l*BB + b)*FF + t)*DD + gw] = acc[b] + bv;
                }
                // prefetch Wo rows for stage B (4 rows: d0..d0+3)
                {
                    const float* Wo = sa_out_w + (size_t)l*DD*DD;
                    int d0 = sub*32 + w*4;
#pragma unroll
                    for (int u = 0; u < 4; u++)
                        pf_row512(swp + u*512, Wo + (size_t)(d0 + u)*DD, lane);
                    cp_commit();
                }
            }
            grid_sync(phase, grp);

            // ==== Stage B: attention (8 warps = 8 heads, batch myb) + out-proj ====
            {
                int h = w;
                if (lane < 16) ((float4*)s_qb[w])[lane] = ((const float4*)(g_q + myb*DD + h*DHH))[lane];
                __syncwarp();
                const float* Kb = g_K + (((size_t)l*BB + myb)*FF)*DD + h*DHH;
                const float* Vb = g_V + (((size_t)l*BB + myb)*FF)*DD + h*DHH;
                float slope = exp2f(-(float)(h + 1));
                int j0 = lane, j1 = lane + 32;
                float sc0 = -1e30f, sc1 = -1e30f;
                if (j0 <= t){
                    const float4* kr = (const float4*)(Kb + (size_t)j0*DD);
                    float a = 0.f;
#pragma unroll
                    for (int i = 0; i < 16; i++) a += dot4(((const float4*)s_qb[w])[i], kr[i]);
                    sc0 = a*0.125f - slope * (float)((t - j0)/30);
                }
                if (j1 <= t){
                    const float4* kr = (const float4*)(Kb + (size_t)j1*DD);
                    float a = 0.f;
#pragma unroll
                    for (int i = 0; i < 16; i++) a += dot4(((const float4*)s_qb[w])[i], kr[i]);
                    sc1 = a*0.125f - slope * (float)((t - j1)/30);
                }
                float m = fmaxf(sc0, sc1);
#pragma unroll
                for (int o = 16; o; o >>= 1) m = fmaxf(m, __shfl_xor_sync(0xffffffffu, m, o));
                float e0 = (j0 <= t) ? expf(sc0 - m) : 0.f;
                float e1 = (j1 <= t) ? expf(sc1 - m) : 0.f;
                float sm = warp_sum(e0 + e1);
                float inv = 1.f / sm;
                s_p[w][j0] = e0 * inv;
                if (j1 < FF) s_p[w][j1] = e1 * inv;
                __syncwarp();
#pragma unroll
                for (int dq = 0; dq < 2; dq++){
                    int d = lane + dq*32;
                    float a = 0.f;
#pragma unroll 4
                    for (int j = 0; j <= t; j++) a += s_p[w][j] * Vb[(size_t)j*DD + d];
                    s_attn[h*DHH + d] = a;
                }
            }
            __syncthreads();
            {
                const float* bo = sa_out_b + (size_t)l*DD;
                cp_wait(); __syncwarp();
                float4 av[4];
#pragma unroll
                for (int q = 0; q < 4; q++) av[q] = ((const float4*)s_attn)[lane + q*32];
#pragma unroll
                for (int uq = 0; uq < 4; uq++){
                    int d = sub*32 + w*4 + uq;
                    const float4* w4 = (const float4*)(swp + uq*512);
                    float a = 0.f;
#pragma unroll
                    for (int q = 0; q < 4; q++) a += dot4(av[q], w4[lane + q*32]);
                    a = warp_sum(a);
                    if (lane == 0) g_r[myb*DD + d] = a + bo[d] + s_x[myb][d];
                }
                // prefetch ff1 rows (gw, gw+1024)
                {
                    const float* W1 = ff1_w + (size_t)l*DFFF*DD;
                    pf_row512(swp,       W1 + (size_t)gw*DD, lane);
                    pf_row512(swp + 512, W1 + (size_t)(gw+1024)*DD, lane);
                    cp_commit();
                }
            }
            grid_sync(phase, grp);

            // ==== Stage C: LN1 + XA + LN2 (warp b per batch) then ff1 ====
            {
                const float4* lng1 = (const float4*)(ln_g + ((size_t)l*3 + 0)*DD);
                const float4* lnb1 = (const float4*)(ln_b + ((size_t)l*3 + 0)*DD);
                const float4* lng2 = (const float4*)(ln_g + ((size_t)l*3 + 1)*DD);
                const float4* lnb2 = (const float4*)(ln_b + ((size_t)l*3 + 1)*DD);
                int b = w;
                const float4* xa4 = (const float4*)(g_XA + (((size_t)l*BB + b)*FF + t)*DD);
                float4 v[4]; float s = 0.f;
#pragma unroll
                for (int q = 0; q < 4; q++){
                    int i = lane + q*32;
                    v[q] = ((const float4*)(g_r + b*DD))[i];
                    s += v[q].x+v[q].y+v[q].z+v[q].w;
                }
                s = warp_sum(s); float mu = s * (1.f/DD);
                float vs = 0.f;
#pragma unroll
                for (int q = 0; q < 4; q++){
                    float dx=v[q].x-mu, dy=v[q].y-mu, dz=v[q].z-mu, dw=v[q].w-mu;
                    vs += dx*dx+dy*dy+dz*dz+dw*dw;
                }
                vs = warp_sum(vs); float rstd = rsqrtf(vs*(1.f/DD) + LNEPS);
                float s2 = 0.f;
#pragma unroll
                for (int q = 0; q < 4; q++){
                    int i = lane + q*32;
                    float4 gg = lng1[i], bb = lnb1[i], xa = xa4[i], r2;
                    r2.x = (v[q].x-mu)*rstd*gg.x + bb.x + xa.x;
                    r2.y = (v[q].y-mu)*rstd*gg.y + bb.y + xa.y;
                    r2.z = (v[q].z-mu)*rstd*gg.z + bb.z + xa.z;
                    r2.w = (v[q].w-mu)*rstd*gg.w + bb.w + xa.w;
                    v[q] = r2; s2 += r2.x+r2.y+r2.z+r2.w;
                }
                s2 = warp_sum(s2); mu = s2 * (1.f/DD);
                vs = 0.f;
#pragma unroll
                for (int q = 0; q < 4; q++){
                    float dx=v[q].x-mu, dy=v[q].y-mu, dz=v[q].z-mu, dw=v[q].w-mu;
                    vs += dx*dx+dy*dy+dz*dz+dw*dw;
                }
                vs = warp_sum(vs); rstd = rsqrtf(vs*(1.f/DD) + LNEPS);
#pragma unroll
                for (int q = 0; q < 4; q++){
                    int i = lane + q*32;
                    float4 gg = lng2[i], bb = lnb2[i], o;
                    o.x = (v[q].x-mu)*rstd*gg.x + bb.x;
                    o.y = (v[q].y-mu)*rstd*gg.y + bb.y;
                    o.z = (v[q].z-mu)*rstd*gg.z + bb.z;
                    o.w = (v[q].w-mu)*rstd*gg.w + bb.w;
                    ((float4*)s_x[b])[i] = o;
                }
            }
            __syncthreads();
            {
                const float* b1 = ff1_b + (size_t)l*DFFF;
                cp_wait(); __syncwarp();
#pragma unroll
                for (int rq = 0; rq < 2; rq++){
                    int rr = gw + rq*1024;
                    const float4* w4 = (const float4*)(swp + rq*512);
                    float acc[8] = {0.f,0.f,0.f,0.f,0.f,0.f,0.f,0.f};
#pragma unroll
                    for (int q = 0; q < 4; q++){
                        int i = lane + q*32;
                        float4 wv = w4[i];
#pragma unroll
                        for (int b = 0; b < 8; b++)
                            acc[b] += dot4(wv, ((const float4*)s_x[b])[i]);
                    }
#pragma unroll
                    for (int o = 16; o; o >>= 1){
#pragma unroll
                        for (int b = 0; b < 8; b++) acc[b] += __shfl_xor_sync(0xffffffffu, acc[b], o);
                    }
                    float bv = b1[rr];
#pragma unroll
                    for (int b = 0; b < 8; b++)
                        if (lane == b) g_h[b*DFFF + rr] = fmaxf(acc[b] + bv, 0.f);
                }
                // prefetch ff2 half-row (1024 floats)
                {
                    int rloc = w >> 1, half = w & 1;
                    int rr2 = blockIdx.x*4 + rloc;
                    pf_row1024(swp, ff2_w + (size_t)l*DD*DFFF + (size_t)rr2*DFFF + half*1024, lane);
                    cp_commit();
                }
            }
            grid_sync(phase, grp);

            // ==== Stage D: ff2 (split-K: 2 warps per output row, staged weights) ====
            {
                int rloc = w >> 1, half = w & 1;
                cp_wait(); __syncwarp();
                const float4* w4 = (const float4*)swp;
                const float* hh = g_h + half*1024;
                float acc[8] = {0.f,0.f,0.f,0.f,0.f,0.f,0.f,0.f};
#pragma unroll
                for (int q = 0; q < 8; q++){
                    int i = lane + q*32;
                    float4 wv = w4[i];
#pragma unroll
                    for (int b = 0; b < 8; b++)
                        acc[b] += dot4(wv, ((const float4*)(hh + (size_t)b*DFFF))[i]);
                }
#pragma unroll
                for (int o = 16; o; o >>= 1){
#pragma unroll
                    for (int b = 0; b < 8; b++) acc[b] += __shfl_xor_sync(0xffffffffu, acc[b], o);
                }
                if (lane < 8) s_d[rloc][half][lane] = acc[lane];
                __syncthreads();
                if (w < 4 && lane < 8){
                    int r2 = blockIdx.x * 4 + w;
                    g_y[lane*DD + r2] = s_d[w][0][lane] + s_d[w][1][lane] + ff2_b[(size_t)l*DD + r2];
                }
                // prefetch next layer's qkv rows
                if (l < LLAY - 1){
                    const float* Wq = sa_in_w + (size_t)(l+1)*3*DD*DD;
                    pf_row512(swp, Wq + (size_t)gw*DD, lane);
                    if (gw < 512) pf_row512(swp + 512, Wq + (size_t)(gw+1024)*DD, lane);
                    cp_commit();
                }
            }
            grid_sync(phase, grp);
        } // layers

        // ==== Stage H: LN3 + head (batch myb, warp-redundant LN) + next emb ====
        {
            const float4* lng3 = (const float4*)(ln_g + (size_t)((LLAY-1)*3 + 2)*DD);
            const float4* lnb3 = (const float4*)(ln_b + (size_t)((LLAY-1)*3 + 2)*DD);
            float4 x3[4]; float s = 0.f;
#pragma unroll
            for (int q = 0; q < 4; q++){
                int i = lane + q*32;
                float4 a = ((const float4*)s_x[myb])[i];
                float4 y = ((const float4*)(g_y + myb*DD))[i];
                x3[q].x = a.x+y.x; x3[q].y = a.y+y.y; x3[q].z = a.z+y.z; x3[q].w = a.w+y.w;
                s += x3[q].x+x3[q].y+x3[q].z+x3[q].w;
            }
            s = warp_sum(s); float mu = s * (1.f/DD);
            float vs = 0.f;
#pragma unroll
            for (int q = 0; q < 4; q++){
                float dx=x3[q].x-mu, dy=x3[q].y-mu, dz=x3[q].z-mu, dw=x3[q].w-mu;
                vs += dx*dx+dy*dy+dz*dz+dw*dw;
            }
            vs = warp_sum(vs); float rstd = rsqrtf(vs*(1.f/DD) + LNEPS);
#pragma unroll
            for (int q = 0; q < 4; q++){
                int i = lane + q*32;
                float4 gg = lng3[i], bb = lnb3[i];
                x3[q].x = (x3[q].x-mu)*rstd*gg.x + bb.x;
                x3[q].y = (x3[q].y-mu)*rstd*gg.y + bb.y;
                x3[q].z = (x3[q].z-mu)*rstd*gg.z + bb.z;
                x3[q].w = (x3[q].w-mu)*rstd*gg.w + bb.w;
            }
#pragma unroll
            for (int jj = 0; jj < 8; jj++){
                int j = w*8 + jj;
                const float4* w4 = (const float4*)(mmr_w + (size_t)j*DD);
                float a = 0.f;
#pragma unroll
                for (int q = 0; q < 4; q++) a += dot4(x3[q], w4[lane + q*32]);
                a = warp_sum(a);
                if (lane == 0){
                    float val = a + mmr_b[j];
                    s_out[j] = val;
                    dec_out[((size_t)myb*FF + t)*MMM + j] = val;
                }
            }
        }
        __syncthreads();
        if (t < FF - 1){
            float o0 = s_out[lane], o1 = s_out[lane + 32];
#pragma unroll
            for (int uq = 0; uq < 4; uq++){
                int d = sub*32 + w*4 + uq;
                const float* cw = g_CW + (size_t)d*MMM;
                float a = o0*cw[lane] + o1*cw[lane + 32];
                a = warp_sum(a);
                if (lane == 0)
                    g_xb[myb*DD + d] = a + g_cb[d] + g_E2[((size_t)myb*FF + t + 1)*DD + d];
            }
            // prefetch qkv(l=0) for next step
            pf_row512(swp, sa_in_w + (size_t)gw*DD, lane);
            if (gw < 512) pf_row512(swp + 512, sa_in_w + (size_t)(gw+1024)*DD, lane);
            cp_commit();
            grid_sync(phase, grp);
        }
    } // steps
}

// ---------------- launch ---------------------------------------------------------
extern "C" void kernel_launch(void* const* d_in, const int* in_sizes, int n_in,
                              void* d_out, int out_size){
    const float* content       = (const float*)d_in[0];
    const float* style_code    = (const float*)d_in[1];
    const float* style_hiddens = (const float*)d_in[2];
    const float* init_state    = (const float*)d_in[3];
    const float* ca_in_w  = (const float*)d_in[4];
    const float* ca_in_b  = (const float*)d_in[5];
    const float* ca_out_w = (const float*)d_in[6];
    const float* ca_out_b = (const float*)d_in[7];
    const float* se_w     = (const float*)d_in[8];
    const float* se_b     = (const float*)d_in[9];
    const float* mm_w     = (const float*)d_in[10];
    const float* mm_b     = (const float*)d_in[11];
    const float* mmr_w    = (const float*)d_in[12];
    const float* mmr_b    = (const float*)d_in[13];
    const float* sa_in_w  = (const float*)d_in[14];
    const float* sa_in_b  = (const float*)d_in[15];
    const float* sa_out_w = (const float*)d_in[16];
    const float* sa_out_b = (const float*)d_in[17];
    const float* xa_in_w  = (const float*)d_in[18];
    const float* xa_in_b  = (const float*)d_in[19];
    const float* xa_out_w = (const float*)d_in[20];
    const float* xa_out_b = (const float*)d_in[21];
    const float* ff1_w    = (const float*)d_in[22];
    const float* ff1_b    = (const float*)d_in[23];
    const float* ff2_w    = (const float*)d_in[24];
    const float* ff2_b    = (const float*)d_in[25];
    const float* ln_g     = (const float*)d_in[26];
    const float* ln_b     = (const float*)d_in[27];

    float* dec_out = (float*)d_out;                      // (B,48,64)
    float* sel     = (float*)d_out + BB*FF*MMM;          // (B,48,512)

    // 64KB dynamic smem opt-in (persists from the uncaptured correctness call)
    cudaFuncSetAttribute(decode_kernel, cudaFuncAttributeMaxDynamicSharedMemorySize, 65536);

    dim3 blk(256);

    // 1) CA in-proj (q/k/v)
    ca_inproj_kernel<<<dim3(64, 64, 3), blk>>>(content, style_hiddens, ca_in_w, ca_in_b);
    // 2) sel attention (in-place on g_qh)
    ca_attn_kernel<<<BB*FF, 256>>>();
    // 3) sel out-proj + XA value-proj (z-fused)
    fused3_kernel<<<dim3(64, 48, 5), blk>>>(content, ca_out_w, ca_out_b, xa_in_w, xa_in_b, sel);
    // 4) XA out-proj
    xa2_kernel<<<dim3(64, 48, LLAY), blk>>>(xa_out_w, xa_out_b);
    // 5) E2 + CW fold + x0 + barrier reset
    misc_kernel<<<3593, 256>>>(sel, se_w, se_b, style_code, mm_w, mm_b, init_state);
    // 6) persistent autoregressive decode
    decode_kernel<<<GRID, 256, 65536>>>(sa_in_w, sa_in_b, sa_out_w, sa_out_b,
                                        ff1_w, ff1_b, ff2_w, ff2_b,
                                        ln_g, ln_b, mmr_w, mmr_b, dec_out);
}